// round 4
// baseline (speedup 1.0000x reference)
#include <cuda_runtime.h>

// Problem constants (fixed shapes per reference)
#define NUM_EDGES 1000000
#define NUM_USERS 50000
#define NUM_ITEMS 20000
#define NRATE 5
#define NFEAT 64
#define KDIM (NRATE * NFEAT)   // 320

// ---------------------------------------------------------------------------
// Scratch: one static device array (no allocation allowed).
//   sum_u [NUM_USERS][5][64]   per-(user,rating) feature sums
//   sum_v [NUM_ITEMS][5][64]
//   cnt_u [NUM_USERS][5]       per-(user,rating) edge counts (float)
//   cnt_v [NUM_ITEMS][5]
// ---------------------------------------------------------------------------
constexpr size_t SUM_U_OFF = 0;
constexpr size_t SUM_V_OFF = (size_t)NUM_USERS * NRATE * NFEAT;              // 16,000,000
constexpr size_t CNT_U_OFF = SUM_V_OFF + (size_t)NUM_ITEMS * NRATE * NFEAT;  // 22,400,000
constexpr size_t CNT_V_OFF = CNT_U_OFF + (size_t)NUM_USERS * NRATE;          // 22,650,000
constexpr size_t SCRATCH_TOTAL = CNT_V_OFF + (size_t)NUM_ITEMS * NRATE;      // 22,750,000 floats (91MB)

__device__ __align__(16) float g_scratch[SCRATCH_TOTAL];

// ---------------------------------------------------------------------------
// PTX helpers
// ---------------------------------------------------------------------------
__device__ __forceinline__ void red_add_v4(float* p, float4 v) {
    unsigned long long gp = (unsigned long long)__cvta_generic_to_global(p);
    asm volatile("red.global.add.v4.f32 [%0], {%1, %2, %3, %4};"
                 :: "l"(gp), "f"(v.x), "f"(v.y), "f"(v.z), "f"(v.w)
                 : "memory");
}

__device__ __forceinline__ unsigned long long pack2(float x, float y) {
    unsigned long long d;
    asm("mov.b64 %0, {%1, %2};" : "=l"(d)
        : "r"(__float_as_uint(x)), "r"(__float_as_uint(y)));
    return d;
}
__device__ __forceinline__ void fma2(unsigned long long& d, unsigned long long a, unsigned long long b) {
    asm("fma.rn.f32x2 %0, %1, %2, %3;" : "=l"(d) : "l"(a), "l"(b), "l"(d));
}
__device__ __forceinline__ void unpack2(unsigned long long d, float& x, float& y) {
    unsigned int lo, hi;
    asm("mov.b64 {%0, %1}, %2;" : "=r"(lo), "=r"(hi) : "l"(d));
    x = __uint_as_float(lo);
    y = __uint_as_float(hi);
}

// ---------------------------------------------------------------------------
// Kernel 1: zero the scratch (float4 stores)
// ---------------------------------------------------------------------------
__global__ void __launch_bounds__(256) zero_kernel() {
    size_t i = (size_t)blockIdx.x * blockDim.x + threadIdx.x;
    float4* p = reinterpret_cast<float4*>(g_scratch);
    if (i < SCRATCH_TOTAL / 4) p[i] = make_float4(0.f, 0.f, 0.f, 0.f);
}

// ---------------------------------------------------------------------------
// Kernel 2: edge scatter. Each 16-lane half-warp owns one edge:
//   lane hl loads float4 of the source feature row (coalesced 256B gather)
//   and issues one red.global.add.v4.f32 per direction.
//   lane 0 bumps the two (dst,rating) counts.
// 8 edges per warp (4 iterations x 2 edges).
// ---------------------------------------------------------------------------
__global__ void __launch_bounds__(256) scatter_kernel(
    const int*   __restrict__ u_s,
    const int*   __restrict__ v_s,
    const int*   __restrict__ rate,
    const float* __restrict__ x_user,
    const float* __restrict__ x_item,
    int E)
{
    int gw   = (blockIdx.x * blockDim.x + threadIdx.x) >> 5;  // global warp
    int lane = threadIdx.x & 31;
    int hl   = lane & 15;
    int sub  = lane >> 4;
    int base = gw * 8;

    #pragma unroll
    for (int it = 0; it < 4; ++it) {
        int e = base + it * 2 + sub;
        if (e >= E) break;  // e is monotone in it -> per-thread break is safe

        int u = __ldg(u_s + e);
        int v = __ldg(v_s + e);
        int r = __ldg(rate + e);

        // user-side aggregation of item features
        float4 xi = reinterpret_cast<const float4*>(x_item + (size_t)v * NFEAT)[hl];
        red_add_v4(g_scratch + SUM_U_OFF + ((size_t)u * NRATE + r) * NFEAT + hl * 4, xi);

        // item-side aggregation of user features
        float4 xu = reinterpret_cast<const float4*>(x_user + (size_t)u * NFEAT)[hl];
        red_add_v4(g_scratch + SUM_V_OFF + ((size_t)v * NRATE + r) * NFEAT + hl * 4, xu);

        if (hl == 0) {
            atomicAdd(g_scratch + CNT_U_OFF + (size_t)u * NRATE + r, 1.0f);
            atomicAdd(g_scratch + CNT_V_OFF + (size_t)v * NRATE + r, 1.0f);
        }
    }
}

// ---------------------------------------------------------------------------
// Kernel 3: transform GEMM.  out[n,h] = sum_k mean[n,k] * W[k,h]
// where k = r*64+d flattens ratings x features (weight is already [k][h]
// row-major), and mean[n,k] = sum[n,k] / max(cnt[n, k/64], 1).
//
// Tile: 64 nodes x 64 h per block, K in chunks of 32. 128 threads:
//   c = t&15 -> h group (4 h's, float4 B reads)
//   g = t>>4 -> node group (8 nodes each)
// Each thread accumulates 8 nodes x 4 h via packed fma.rn.f32x2.
//
// As stride = 65: the paired A-stagers (ks=0 vs ks=16) land 1040 floats
// apart -> bank offset 16 -> conflict-free STS (stride 68 put them 1088
// apart = same bank, a guaranteed 2-way conflict).
// ---------------------------------------------------------------------------
__global__ void __launch_bounds__(128) transform_kernel(
    const float* __restrict__ W,
    float*       __restrict__ out,
    size_t sum_off, size_t cnt_off, int n_nodes)
{
    __shared__ float As[32][65];   // [k][node]
    __shared__ float Bs[32][64];   // [k][h]

    const float* sums = g_scratch + sum_off;
    const float* cnts = g_scratch + cnt_off;

    int t = threadIdx.x;
    int c = t & 15;     // h-group: h = 4c..4c+3
    int g = t >> 4;     // node-group: nodes g*8..g*8+7
    int nodeBase = blockIdx.x * 64;

    // A-staging role: thread t loads node (t>>1), k-halves of 16
    int nLoc = t >> 1;
    int ks   = (t & 1) * 16;

    unsigned long long acc01[8], acc23[8];
    #pragma unroll
    for (int i = 0; i < 8; ++i) { acc01[i] = 0ull; acc23[i] = 0ull; }

    for (int kc = 0; kc < KDIM / 32; ++kc) {
        int k0 = kc * 32;
        int r  = k0 >> 6;          // rating constant per 32-chunk (chunks align inside 64)

        // ---- stage A: mean = sum * (1/max(cnt,1)) ----
        {
            int n = nodeBase + nLoc;
            bool valid = (n < n_nodes);
            float inv = 0.f;
            if (valid) inv = 1.0f / fmaxf(cnts[(size_t)n * NRATE + r], 1.0f);
            const float* src = sums + (size_t)n * KDIM + k0 + ks;
            #pragma unroll
            for (int j = 0; j < 16; j += 4) {
                float4 s = valid ? *reinterpret_cast<const float4*>(src + j)
                                 : make_float4(0.f, 0.f, 0.f, 0.f);
                As[ks + j + 0][nLoc] = s.x * inv;
                As[ks + j + 1][nLoc] = s.y * inv;
                As[ks + j + 2][nLoc] = s.z * inv;
                As[ks + j + 3][nLoc] = s.w * inv;
            }
        }
        // ---- stage B: weight chunk [32][64] (coalesced float4) ----
        {
            const float4* wsrc = reinterpret_cast<const float4*>(W + (size_t)k0 * 64);
            float4* bdst = reinterpret_cast<float4*>(&Bs[0][0]);
            #pragma unroll
            for (int j = 0; j < 4; ++j) bdst[t + j * 128] = wsrc[t + j * 128];
        }
        __syncthreads();

        // ---- compute: 32 k-steps, packed f32x2 FMAs ----
        #pragma unroll 8
        for (int k = 0; k < 32; ++k) {
            float4 b = *reinterpret_cast<const float4*>(&Bs[k][c * 4]);
            unsigned long long bxy = pack2(b.x, b.y);
            unsigned long long bzw = pack2(b.z, b.w);
            #pragma unroll
            for (int i = 0; i < 8; ++i) {
                float a = As[k][g * 8 + i];
                unsigned long long aa = pack2(a, a);
                fma2(acc01[i], aa, bxy);
                fma2(acc23[i], aa, bzw);
            }
        }
        __syncthreads();
    }

    #pragma unroll
    for (int i = 0; i < 8; ++i) {
        int n = nodeBase + g * 8 + i;
        if (n < n_nodes) {
            float4 o;
            unpack2(acc01[i], o.x, o.y);
            unpack2(acc23[i], o.z, o.w);
            *reinterpret_cast<float4*>(out + (size_t)n * NFEAT + c * 4) = o;
        }
    }
}

// ---------------------------------------------------------------------------
// Launch
// ---------------------------------------------------------------------------
extern "C" void kernel_launch(void* const* d_in, const int* in_sizes, int n_in,
                              void* d_out, int out_size)
{
    const int*   u_s    = (const int*)  d_in[0];
    const int*   v_s    = (const int*)  d_in[1];
    const int*   rate   = (const int*)  d_in[2];
    const float* x_user = (const float*)d_in[3];
    const float* x_item = (const float*)d_in[4];
    const float* weight = (const float*)d_in[5];
    float* out = (float*)d_out;

    int E = in_sizes[0];

    int zblocks = (int)((SCRATCH_TOTAL / 4 + 255) / 256);
    zero_kernel<<<zblocks, 256>>>();

    int sblocks = (E + 63) / 64;   // 64 edges per 256-thread block (8/warp)
    scatter_kernel<<<sblocks, 256>>>(u_s, v_s, rate, x_user, x_item, E);

    transform_kernel<<<(NUM_USERS + 63) / 64, 128>>>(
        weight, out, SUM_U_OFF, CNT_U_OFF, NUM_USERS);
    transform_kernel<<<(NUM_ITEMS + 63) / 64, 128>>>(
        weight, out + (size_t)NUM_USERS * NFEAT, SUM_V_OFF, CNT_V_OFF, NUM_ITEMS);
}